// round 12
// baseline (speedup 1.0000x reference)
#include <cuda_runtime.h>
#include <cuda_bf16.h>
#include <stdint.h>

// ---------------- problem constants ----------------
#define BB     4
#define CCH    256          // FIN
#define SS     4096         // H*W
#define MP     (BB*SS)      // 16384 positions
#define NMEM   64
#define SQG    16
#define QKROWS 2048         // 1024 q rows + 1024 k rows
#define CINR   258          // FIN + 2 pos channels
#define KPAD   288          // CINR padded: 4x64 + 1x32 k-tiles
#define NKT    5

// ---------------- scratch (device globals; no allocation) ----------------
__device__ __nv_bfloat16 g_A[(size_t)MP * KPAD];          // xp^T bf16, K padded
__device__ __nv_bfloat16 g_W[(size_t)QKROWS * KPAD];      // [wq; wk] bf16, K padded
__device__ float         g_attn[(size_t)MP * NMEM];       // attn_mean per position
__device__ float         g_Wv[NMEM * CCH];                // v @ wout^T (fused tail)

// ---------------- PTX helpers (base sm_103 only) ----------------
__device__ __forceinline__ uint32_t smem_u32(const void* p) {
    uint32_t a;
    asm("{ .reg .u64 t; cvta.to.shared.u64 t, %1; cvt.u32.u64 %0, t; }" : "=r"(a) : "l"(p));
    return a;
}
__device__ __forceinline__ void cp16(uint32_t saddr, const void* g) {
    asm volatile("cp.async.cg.shared.global [%0], [%1], 16;\n" :: "r"(saddr), "l"(g));
}
__device__ __forceinline__ void cp_commit() {
    asm volatile("cp.async.commit_group;\n" ::: "memory");
}
template <int N> __device__ __forceinline__ void cp_wait() {
    asm volatile("cp.async.wait_group %0;\n" :: "n"(N) : "memory");
}
__device__ __forceinline__ void mma16816(float* c, const unsigned* a, const unsigned* b) {
    asm volatile(
        "mma.sync.aligned.m16n8k16.row.col.f32.bf16.bf16.f32 "
        "{%0,%1,%2,%3}, {%4,%5,%6,%7}, {%8,%9}, {%0,%1,%2,%3};\n"
        : "+f"(c[0]), "+f"(c[1]), "+f"(c[2]), "+f"(c[3])
        : "r"(a[0]), "r"(a[1]), "r"(a[2]), "r"(a[3]), "r"(b[0]), "r"(b[1]));
}
__device__ __forceinline__ void ldsm_x4(unsigned& r0, unsigned& r1, unsigned& r2,
                                        unsigned& r3, uint32_t a) {
    asm volatile("ldmatrix.sync.aligned.m8n8.x4.shared.b16 {%0,%1,%2,%3}, [%4];"
                 : "=r"(r0), "=r"(r1), "=r"(r2), "=r"(r3) : "r"(a));
}
// SW128 swizzle for 128-byte rows
__device__ __forceinline__ uint32_t swz(uint32_t off) { return off ^ ((off >> 3) & 0x70); }

// ---------------- prep: transpose x into g_A (cols 0..255) ----------------
__global__ void prep_x_kernel(const float* __restrict__ x) {
    __shared__ float tile[32][33];
    int b  = blockIdx.z;
    int c0 = blockIdx.x * 32;
    int s0 = blockIdx.y * 32;
    int tx = threadIdx.x, ty = threadIdx.y;  // 32 x 8
    const float* xb = x + (size_t)b * CCH * SS;
#pragma unroll
    for (int i = 0; i < 4; i++) {
        int c = c0 + ty + i * 8;
        tile[ty + i * 8][tx] = xb[(size_t)c * SS + s0 + tx];
    }
    __syncthreads();
#pragma unroll
    for (int i = 0; i < 4; i++) {
        int s = s0 + ty + i * 8;
        int p = b * SS + s;
        g_A[(size_t)p * KPAD + c0 + tx] = __float2bfloat16(tile[tx][ty + i * 8]);
    }
}

// ---------------- prep: pos channels + zero pad (cols 256..287) ----------------
__global__ void prep_pos_kernel(const float* __restrict__ pos) {
    int g = blockIdx.x * blockDim.x + threadIdx.x;   // MP*32 threads
    int p = g >> 5, cc = g & 31;
    int s = p & (SS - 1);
    float v = 0.f;
    if (cc == 0)      v = pos[s];
    else if (cc == 1) v = pos[SS + s];
    g_A[(size_t)p * KPAD + 256 + cc] = __float2bfloat16(v);
}

// ---------------- prep: weights [wq; wk] -> bf16 padded ----------------
__global__ void prep_w_kernel(const float* __restrict__ wq, const float* __restrict__ wk) {
    int g = blockIdx.x * blockDim.x + threadIdx.x;   // QKROWS*KPAD threads
    int r = g / KPAD, c = g % KPAD;
    float v = 0.f;
    if (c < CINR) v = (r < 1024) ? wq[r * CINR + c] : wk[(r - 1024) * CINR + c];
    g_W[g] = __float2bfloat16(v);
}

// ---------------- prep: Wv[m][o] = sum_f v[m][f] * wout[o][f] ----------------
// grid (NMEM, 8); block 256 = 32 o-lanes x 8 f-eighths; smem reduce, no atomics.
__global__ __launch_bounds__(256) void prep_wv_kernel(const float* __restrict__ v,
                                                      const float* __restrict__ wout) {
    __shared__ float vs[CCH];
    __shared__ float part[256];
    int m  = blockIdx.x;
    int oc = blockIdx.y;          // chunk of 32 outputs
    int tid = threadIdx.x;
    int ol = tid & 31, fq = tid >> 5;
    vs[tid] = v[m * CCH + tid];
    __syncthreads();
    int o = oc * 32 + ol;
    const float4* wr = reinterpret_cast<const float4*>(wout + (size_t)o * CCH + fq * 32);
    float acc = 0.f;
#pragma unroll
    for (int i = 0; i < 8; i++) {
        float4 w = wr[i];
        int f = fq * 32 + i * 4;
        acc += vs[f] * w.x + vs[f + 1] * w.y + vs[f + 2] * w.z + vs[f + 3] * w.w;
    }
    part[tid] = acc;
    __syncthreads();
    if (fq == 0) {
        float s = 0.f;
#pragma unroll
        for (int k = 0; k < 8; k++) s += part[ol + 32 * k];
        g_Wv[m * CCH + o] = s;
    }
}

// ---------------- fused GEMM + attention ----------------
// One block: 128 positions x ALL 2048 outputs. A resident in smem; B streamed
// per 128-wide n-chunk (16 chunks: 8 q then 8 k). Per-chunk epilogue does the
// slot normalization; q-chunks accumulate sum of normalized q; k-chunks emit attn.
#define FBM 128
#define NCH 16
#define SA_OFF 0                    // 5 x 16384 = 81920 (kt4 half-used)
#define SB_OFF 81920                // 2 x 16384
#define QS_OFF 114688               // 128 x 17 x 4 = 8704
#define BQ_OFF 123392               // 1024 x 4
#define BK_OFF 127488               // 1024 x 4
#define SMF_TOTAL 131584
#define QSP 17                      // qs_sum row pitch (floats)

__global__ __launch_bounds__(256, 1) void gemm_attn_kernel(const float* __restrict__ bq,
                                                           const float* __restrict__ bk) {
    extern __shared__ __align__(1024) char smem[];
    uint32_t sbase = smem_u32(smem);
    float* qs_s = reinterpret_cast<float*>(smem + QS_OFF);
    float* bq_s = reinterpret_cast<float*>(smem + BQ_OFF);
    float* bk_s = reinterpret_cast<float*>(smem + BK_OFF);
    int tid  = threadIdx.x;
    int warp = tid >> 5, lane = tid & 31;
    int wm = warp & 1, wn = warp >> 1;          // 2(m) x 4(n)
    int gr = lane >> 2, tg = lane & 3;
    int m0 = blockIdx.x * FBM;

    // ldmatrix lane geometry
    int j8  = lane >> 3;
    int jm  = j8 & 1;
    uint32_t kadd = (uint32_t)(j8 >> 1) * 16;
    uint32_t xorv = (uint32_t)(lane & 7) << 4;
    int rA[4], rB[2];
#pragma unroll
    for (int mf = 0; mf < 4; mf++) rA[mf] = wm * 64 + mf * 16 + jm * 8 + (lane & 7);
#pragma unroll
    for (int nh = 0; nh < 2; nh++) rB[nh] = wn * 32 + nh * 16 + jm * 8 + (lane & 7);

    // ---- prologue: stage B(chunk0,kt0), all of A; zero qs; load biases ----
    {   // B chunk 0, kt 0 (64-wide)
#pragma unroll
        for (int i = 0; i < 4; i++) {
            int idx = tid + i * 256;
            int row = idx >> 3, ch = idx & 7;
            cp16(sbase + SB_OFF + swz(row * 128 + ch * 16),
                 &g_W[(size_t)row * KPAD + ch * 8]);
        }
        cp_commit();
    }
#pragma unroll
    for (int kt = 0; kt < 4; kt++) {           // A kt 0..3 (64-wide)
#pragma unroll
        for (int i = 0; i < 4; i++) {
            int idx = tid + i * 256;
            int row = idx >> 3, ch = idx & 7;
            cp16(sbase + SA_OFF + kt * 16384 + swz(row * 128 + ch * 16),
                 &g_A[(size_t)(m0 + row) * KPAD + kt * 64 + ch * 8]);
        }
    }
    {   // A kt 4 (32-wide)
#pragma unroll
        for (int i = 0; i < 2; i++) {
            int idx = tid + i * 256;
            int row = idx >> 2, ch = idx & 3;
            cp16(sbase + SA_OFF + 4 * 16384 + swz(row * 128 + ch * 16),
                 &g_A[(size_t)(m0 + row) * KPAD + 256 + ch * 8]);
        }
        cp_commit();
    }
    for (int i = tid; i < FBM * QSP; i += 256) qs_s[i] = 0.f;
    for (int i = tid; i < 1024; i += 256) { bq_s[i] = bq[i]; bk_s[i] = bk[i]; }

    float acc[4][4][4];
#pragma unroll
    for (int a1 = 0; a1 < 4; a1++)
#pragma unroll
        for (int a2 = 0; a2 < 4; a2++)
#pragma unroll
            for (int a3 = 0; a3 < 4; a3++) acc[a1][a2][a3] = 0.f;
    float qp[8][4];
#pragma unroll
    for (int a1 = 0; a1 < 8; a1++)
#pragma unroll
        for (int a2 = 0; a2 < 4; a2++) qp[a1][a2] = 0.f;

    int chunk = 0, kt = 0;
    for (int it = 0; it < NCH * NKT; it++) {
        int buf = it & 1;
        // prefetch next B tile into buf^1
        if (it + 1 < NCH * NKT) {
            int nkt = kt + 1, nchunk = chunk;
            if (nkt == NKT) { nkt = 0; nchunk++; }
            int n0 = nchunk * 128, kk = nkt * 64;
            uint32_t bdst = sbase + SB_OFF + (buf ^ 1) * 16384;
            if (nkt < 4) {
#pragma unroll
                for (int i = 0; i < 4; i++) {
                    int idx = tid + i * 256;
                    int row = idx >> 3, ch = idx & 7;
                    cp16(bdst + swz(row * 128 + ch * 16),
                         &g_W[(size_t)(n0 + row) * KPAD + kk + ch * 8]);
                }
            } else {
#pragma unroll
                for (int i = 0; i < 2; i++) {
                    int idx = tid + i * 256;
                    int row = idx >> 2, ch = idx & 3;
                    cp16(bdst + swz(row * 128 + ch * 16),
                         &g_W[(size_t)(n0 + row) * KPAD + kk + ch * 8]);
                }
            }
            cp_commit();
            cp_wait<1>();
        } else {
            cp_wait<0>();
        }
        __syncthreads();

        // ---- compute this (chunk, kt) tile ----
        uint32_t abase[4], bbase[2];
#pragma unroll
        for (int mf = 0; mf < 4; mf++)
            abase[mf] = sbase + SA_OFF + kt * 16384 + rA[mf] * 128;
#pragma unroll
        for (int nh = 0; nh < 2; nh++)
            bbase[nh] = sbase + SB_OFF + buf * 16384 + rB[nh] * 128;
        int kend = (kt == 4) ? 32 : 64;
#pragma unroll
        for (int ks = 0; ks < 64; ks += 16) {
            if (ks >= kend) break;
            uint32_t cofs = ((uint32_t)(ks * 2) + kadd) ^ xorv;
            unsigned afr[4][4];
#pragma unroll
            for (int mf = 0; mf < 4; mf++)
                ldsm_x4(afr[mf][0], afr[mf][1], afr[mf][2], afr[mf][3], abase[mf] + cofs);
            unsigned bfr[4][2];
#pragma unroll
            for (int nh = 0; nh < 2; nh++) {
                unsigned r0, r1, r2, r3;
                ldsm_x4(r0, r1, r2, r3, bbase[nh] + cofs);
                bfr[nh * 2][0] = r0; bfr[nh * 2 + 1][0] = r1;
                bfr[nh * 2][1] = r2; bfr[nh * 2 + 1][1] = r3;
            }
#pragma unroll
            for (int mf = 0; mf < 4; mf++)
#pragma unroll
                for (int nf = 0; nf < 4; nf++)
                    mma16816(acc[mf][nf], afr[mf], bfr[nf]);
        }
        __syncthreads();   // protect B buf before next prefetch targets it

        // ---- per-chunk epilogue after last k-tile ----
        if (kt == NKT - 1) {
            bool isQ = (chunk < 8);
            int j0 = tg * 2;
#pragma unroll
            for (int p = 0; p < 2; p++) {
                int slot = (chunk & 7) * 8 + wn * 2 + p;
                const float* bs = isQ ? bq_s : bk_s;
                float b0 = bs[slot * 16 + j0];
                float b1 = bs[slot * 16 + j0 + 1];
                float b2 = bs[slot * 16 + j0 + 8];
                float b3 = bs[slot * 16 + j0 + 9];
#pragma unroll
                for (int mf = 0; mf < 4; mf++) {
#pragma unroll
                    for (int h = 0; h < 2; h++) {
                        float v0 = acc[mf][2 * p][2 * h] + b0;
                        float v1 = acc[mf][2 * p][2 * h + 1] + b1;
                        float v2 = acc[mf][2 * p + 1][2 * h] + b2;
                        float v3 = acc[mf][2 * p + 1][2 * h + 1] + b3;
                        float ssq = v0 * v0 + v1 * v1 + v2 * v2 + v3 * v3;
                        if (isQ) {
                            ssq += __shfl_xor_sync(0xffffffffu, ssq, 1);
                            ssq += __shfl_xor_sync(0xffffffffu, ssq, 2);
                            float inv = 1.f / fmaxf(sqrtf(ssq), 1e-12f);
                            qp[mf * 2 + h][0] += v0 * inv;
                            qp[mf * 2 + h][1] += v1 * inv;
                            qp[mf * 2 + h][2] += v2 * inv;
                            qp[mf * 2 + h][3] += v3 * inv;
                        } else {
                            int row = wm * 64 + mf * 16 + gr + h * 8;
                            float q0 = qs_s[row * QSP + j0];
                            float q1 = qs_s[row * QSP + j0 + 1];
                            float q2 = qs_s[row * QSP + j0 + 8];
                            float q3 = qs_s[row * QSP + j0 + 9];
                            float dl = v0 * q0 + v1 * q1 + v2 * q2 + v3 * q3;
                            ssq += __shfl_xor_sync(0xffffffffu, ssq, 1);
                            ssq += __shfl_xor_sync(0xffffffffu, ssq, 2);
                            dl  += __shfl_xor_sync(0xffffffffu, dl, 1);
                            dl  += __shfl_xor_sync(0xffffffffu, dl, 2);
                            float inv = 1.f / fmaxf(sqrtf(ssq), 1e-12f);
                            if (tg == 0)
                                g_attn[(size_t)(m0 + row) * NMEM + slot] =
                                    dl * inv * (1.f / 64.f);
                        }
                    }
                }
            }
            // reset accumulators for next chunk
#pragma unroll
            for (int a1 = 0; a1 < 4; a1++)
#pragma unroll
                for (int a2 = 0; a2 < 4; a2++)
#pragma unroll
                    for (int a3 = 0; a3 < 4; a3++) acc[a1][a2][a3] = 0.f;
            // after last q-chunk: flush qp into qs_sum (cross-warp reduce)
            if (chunk == 7) {
#pragma unroll
                for (int mf = 0; mf < 4; mf++) {
#pragma unroll
                    for (int h = 0; h < 2; h++) {
                        int row = wm * 64 + mf * 16 + gr + h * 8;
                        atomicAdd(&qs_s[row * QSP + j0],     qp[mf * 2 + h][0]);
                        atomicAdd(&qs_s[row * QSP + j0 + 1], qp[mf * 2 + h][1]);
                        atomicAdd(&qs_s[row * QSP + j0 + 8], qp[mf * 2 + h][2]);
                        atomicAdd(&qs_s[row * QSP + j0 + 9], qp[mf * 2 + h][3]);
                    }
                }
                __syncthreads();
            }
        }
        if (++kt == NKT) { kt = 0; chunk++; }
    }
}

// ---------------- output: out = x + attn @ Wv + bout, written [B,256,H,W] ----------------
__global__ __launch_bounds__(256) void out_kernel(const float* __restrict__ x,
                                                  const float* __restrict__ bout,
                                                  float* __restrict__ out) {
    __shared__ float attn_s[64][65];
    __shared__ __align__(16) float wv_s[64][32];
    int p0 = blockIdx.x * 64;
    int o0 = blockIdx.y * 32;
    int tid = threadIdx.x;
    int px = tid & 63, oq = tid >> 6;

#pragma unroll
    for (int i = 0; i < 16; i++) {
        int idx = tid + i * 256;
        int pr = idx >> 6, mm = idx & 63;
        attn_s[pr][mm] = g_attn[(size_t)(p0 + pr) * NMEM + mm];
    }
#pragma unroll
    for (int i = 0; i < 8; i++) {
        int idx = tid + i * 256;
        int mm = idx >> 5, oo = idx & 31;
        wv_s[mm][oo] = g_Wv[mm * CCH + o0 + oo];
    }
    __syncthreads();

    float acc[8];
#pragma unroll
    for (int i = 0; i < 8; i++) acc[i] = 0.f;

#pragma unroll 4
    for (int m = 0; m < 64; m++) {
        float a = attn_s[px][m];
        float4 w0 = *reinterpret_cast<const float4*>(&wv_s[m][oq * 8]);
        float4 w1 = *reinterpret_cast<const float4*>(&wv_s[m][oq * 8 + 4]);
        acc[0] += a * w0.x; acc[1] += a * w0.y; acc[2] += a * w0.z; acc[3] += a * w0.w;
        acc[4] += a * w1.x; acc[5] += a * w1.y; acc[6] += a * w1.z; acc[7] += a * w1.w;
    }

    int p = p0 + px;
    int b = p >> 12, s = p & (SS - 1);
#pragma unroll
    for (int i = 0; i < 8; i++) {
        int o = o0 + oq * 8 + i;
        size_t gi = ((size_t)b * CCH + o) * SS + s;
        out[gi] = x[gi] + acc[i] + bout[o];
    }
}

// ---------------- launch ----------------
extern "C" void kernel_launch(void* const* d_in, const int* in_sizes, int n_in,
                              void* d_out, int out_size) {
    const float* x    = (const float*)d_in[0];
    const float* pos  = (const float*)d_in[1];
    const float* wq   = (const float*)d_in[2];
    const float* bq   = (const float*)d_in[3];
    const float* wk   = (const float*)d_in[4];
    const float* bk   = (const float*)d_in[5];
    const float* v    = (const float*)d_in[6];
    const float* wout = (const float*)d_in[7];
    const float* bout = (const float*)d_in[8];
    float* out = (float*)d_out;

    cudaFuncSetAttribute(gemm_attn_kernel,
                         cudaFuncAttributeMaxDynamicSharedMemorySize, SMF_TOTAL);

    prep_x_kernel<<<dim3(CCH / 32, SS / 32, BB), dim3(32, 8)>>>(x);
    prep_pos_kernel<<<(MP * 32) / 256, 256>>>(pos);
    prep_w_kernel<<<(QKROWS * KPAD) / 256, 256>>>(wq, wk);
    prep_wv_kernel<<<dim3(NMEM, 8), 256>>>(v, wout);
    gemm_attn_kernel<<<MP / FBM, 256, SMF_TOTAL>>>(bq, bk);
    out_kernel<<<dim3(MP / 64, CCH / 32), 256>>>(x, bout, out);
}

// round 13
// speedup vs baseline: 1.1316x; 1.1316x over previous
#include <cuda_runtime.h>
#include <cuda_bf16.h>
#include <stdint.h>

// ---------------- problem constants ----------------
#define BB     4
#define CCH    256          // FIN
#define SS     4096         // H*W
#define MP     (BB*SS)      // 16384 positions
#define NMEM   64
#define SQG    16
#define QKROWS 2048         // 1024 q rows + 1024 k rows
#define CINR   258          // FIN + 2 pos channels
#define KPAD   288          // CINR padded: 4x64 + 1x32 k-tiles
#define NKT    5

// ---------------- scratch (device globals; no allocation) ----------------
__device__ __nv_bfloat16 g_A[(size_t)MP * KPAD];          // xp^T bf16, K padded
__device__ __nv_bfloat16 g_W[(size_t)QKROWS * KPAD];      // [wq; wk] bf16, K padded
__device__ __nv_bfloat16 g_QK[(size_t)MP * QKROWS];       // q,k per position (bf16)
__device__ float         g_attn[(size_t)MP * NMEM];       // attn_mean per position
__device__ float         g_Wv[NMEM * CCH];                // v @ wout^T (fused tail)

// ---------------- PTX helpers (base sm_103 only) ----------------
__device__ __forceinline__ uint32_t smem_u32(const void* p) {
    uint32_t a;
    asm("{ .reg .u64 t; cvta.to.shared.u64 t, %1; cvt.u32.u64 %0, t; }" : "=r"(a) : "l"(p));
    return a;
}
__device__ __forceinline__ void cp16(uint32_t saddr, const void* g) {
    asm volatile("cp.async.cg.shared.global [%0], [%1], 16;\n" :: "r"(saddr), "l"(g));
}
__device__ __forceinline__ void cp_commit() {
    asm volatile("cp.async.commit_group;\n" ::: "memory");
}
template <int N> __device__ __forceinline__ void cp_wait() {
    asm volatile("cp.async.wait_group %0;\n" :: "n"(N) : "memory");
}
__device__ __forceinline__ void mma16816(float* c, const unsigned* a, const unsigned* b) {
    asm volatile(
        "mma.sync.aligned.m16n8k16.row.col.f32.bf16.bf16.f32 "
        "{%0,%1,%2,%3}, {%4,%5,%6,%7}, {%8,%9}, {%0,%1,%2,%3};\n"
        : "+f"(c[0]), "+f"(c[1]), "+f"(c[2]), "+f"(c[3])
        : "r"(a[0]), "r"(a[1]), "r"(a[2]), "r"(a[3]), "r"(b[0]), "r"(b[1]));
}
__device__ __forceinline__ void ldsm_x4(unsigned& r0, unsigned& r1, unsigned& r2,
                                        unsigned& r3, uint32_t a) {
    asm volatile("ldmatrix.sync.aligned.m8n8.x4.shared.b16 {%0,%1,%2,%3}, [%4];"
                 : "=r"(r0), "=r"(r1), "=r"(r2), "=r"(r3) : "r"(a));
}
// SW128 swizzle for 128-byte rows
__device__ __forceinline__ uint32_t swz(uint32_t off) { return off ^ ((off >> 3) & 0x70); }

// ---------------- prep: transpose x into g_A (cols 0..255) ----------------
__global__ void prep_x_kernel(const float* __restrict__ x) {
    __shared__ float tile[32][33];
    int b  = blockIdx.z;
    int c0 = blockIdx.x * 32;
    int s0 = blockIdx.y * 32;
    int tx = threadIdx.x, ty = threadIdx.y;  // 32 x 8
    const float* xb = x + (size_t)b * CCH * SS;
#pragma unroll
    for (int i = 0; i < 4; i++) {
        int c = c0 + ty + i * 8;
        tile[ty + i * 8][tx] = xb[(size_t)c * SS + s0 + tx];
    }
    __syncthreads();
#pragma unroll
    for (int i = 0; i < 4; i++) {
        int s = s0 + ty + i * 8;
        int p = b * SS + s;
        g_A[(size_t)p * KPAD + c0 + tx] = __float2bfloat16(tile[tx][ty + i * 8]);
    }
}

// ---------------- prep: pos channels + zero pad (cols 256..287) ----------------
__global__ void prep_pos_kernel(const float* __restrict__ pos) {
    int g = blockIdx.x * blockDim.x + threadIdx.x;   // MP*32 threads
    int p = g >> 5, cc = g & 31;
    int s = p & (SS - 1);
    float v = 0.f;
    if (cc == 0)      v = pos[s];
    else if (cc == 1) v = pos[SS + s];
    g_A[(size_t)p * KPAD + 256 + cc] = __float2bfloat16(v);
}

// ---------------- prep: weights [wq; wk] -> bf16 padded ----------------
__global__ void prep_w_kernel(const float* __restrict__ wq, const float* __restrict__ wk) {
    int g = blockIdx.x * blockDim.x + threadIdx.x;   // QKROWS*KPAD threads
    int r = g / KPAD, c = g % KPAD;
    float v = 0.f;
    if (c < CINR) v = (r < 1024) ? wq[r * CINR + c] : wk[(r - 1024) * CINR + c];
    g_W[g] = __float2bfloat16(v);
}

// ---------------- prep: Wv[m][o] = sum_f v[m][f] * wout[o][f] ----------------
// grid (NMEM, 4); block 256 = 64 o-lanes x 4 f-quarters; smem reduce, no atomics.
__global__ __launch_bounds__(256) void prep_wv_kernel(const float* __restrict__ v,
                                                      const float* __restrict__ wout) {
    __shared__ float vs[CCH];
    __shared__ float part[256];
    int m  = blockIdx.x;
    int oc = blockIdx.y;          // chunk of 64 outputs
    int tid = threadIdx.x;
    int ol = tid & 63, fq = tid >> 6;
    vs[tid] = v[m * CCH + tid];
    __syncthreads();
    int o = oc * 64 + ol;
    const float4* wr = reinterpret_cast<const float4*>(wout + (size_t)o * CCH + fq * 64);
    float acc = 0.f;
#pragma unroll
    for (int i = 0; i < 16; i++) {
        float4 w = wr[i];
        int f = fq * 64 + i * 4;
        acc += vs[f] * w.x + vs[f + 1] * w.y + vs[f + 2] * w.z + vs[f + 3] * w.w;
    }
    part[tid] = acc;
    __syncthreads();
    if (fq == 0)
        g_Wv[m * CCH + o] = part[ol] + part[ol + 64] + part[ol + 128] + part[ol + 192];
}

// ---------------- GEMM: g_QK[p][n] = sum_k g_A[p][k] * g_W[n][k] ----------------
// 128x128 block tile, K tiles 4x64 + 1x32, 2x4 warp grid, cp.async double buffer,
// SW128-swizzled smem, ldmatrix.x4 fragment loads.
#define GBM 128
#define GBN 128
#define STAGE_A   16384                 // bytes per tile buffer (128 x 128B rows)
#define SM_AOFF(s) ((s) * STAGE_A)
#define SM_BOFF(s) (32768 + (s) * STAGE_A)
#define SM_TOTAL   65536

__device__ __forceinline__ void stage_tile(uint32_t sbase, uint32_t aoff, uint32_t boff,
                                           int m0, int n0, int kt, int tid) {
    int kk = kt * 64;
    if (kt < 4) {          // full 64-wide tile: 128 rows x 8 x 16B
#pragma unroll
        for (int i = 0; i < 4; i++) {
            int idx = tid + i * 256;
            int row = idx >> 3, ch = idx & 7;
            uint32_t so = swz(row * 128 + ch * 16);
            cp16(sbase + aoff + so, &g_A[(size_t)(m0 + row) * KPAD + kk + ch * 8]);
            cp16(sbase + boff + so, &g_W[(size_t)(n0 + row) * KPAD + kk + ch * 8]);
        }
    } else {               // last 32-wide tile: 128 rows x 4 x 16B
#pragma unroll
        for (int i = 0; i < 2; i++) {
            int idx = tid + i * 256;
            int row = idx >> 2, ch = idx & 3;
            uint32_t so = swz(row * 128 + ch * 16);
            cp16(sbase + aoff + so, &g_A[(size_t)(m0 + row) * KPAD + kk + ch * 8]);
            cp16(sbase + boff + so, &g_W[(size_t)(n0 + row) * KPAD + kk + ch * 8]);
        }
    }
    cp_commit();
}

__global__ __launch_bounds__(256, 2) void gemm_qk_kernel() {
    extern __shared__ __align__(1024) char smem[];
    uint32_t sbase = smem_u32(smem);
    int tid  = threadIdx.x;
    int warp = tid >> 5, lane = tid & 31;
    int wm = warp & 1, wn = warp >> 1;      // warp grid 2(m) x 4(n)
    int gr = lane >> 2, tg = lane & 3;
    int m0 = blockIdx.x * GBM;
    int n0 = blockIdx.y * GBN;

    // ldmatrix lane geometry: j = lane>>3 selects the 8x8 matrix
    int j  = lane >> 3;
    int jm = j & 1;                            // +8 rows
    uint32_t kadd = (uint32_t)(j >> 1) * 16;   // +8 k-elems (bytes)
    uint32_t xorv = (uint32_t)(lane & 7) << 4; // swizzle XOR (row & 7)
    int rA[4], rB[2];
#pragma unroll
    for (int mf = 0; mf < 4; mf++) rA[mf] = wm * 64 + mf * 16 + jm * 8 + (lane & 7);
#pragma unroll
    for (int nh = 0; nh < 2; nh++) rB[nh] = wn * 32 + nh * 16 + jm * 8 + (lane & 7);

    float acc[4][4][4];
#pragma unroll
    for (int i = 0; i < 4; i++)
#pragma unroll
        for (int jj = 0; jj < 4; jj++)
#pragma unroll
            for (int q = 0; q < 4; q++) acc[i][jj][q] = 0.f;

    // prologue: stage tile 0 into buffer 0
    stage_tile(sbase, SM_AOFF(0), SM_BOFF(0), m0, n0, 0, tid);

    for (int kt = 0; kt < NKT; kt++) {
        uint32_t aoff = SM_AOFF(kt & 1);
        uint32_t boff = SM_BOFF(kt & 1);
        if (kt + 1 < NKT) {
            stage_tile(sbase, SM_AOFF((kt + 1) & 1), SM_BOFF((kt + 1) & 1),
                       m0, n0, kt + 1, tid);
            cp_wait<1>();
        } else {
            cp_wait<0>();
        }
        __syncthreads();

        uint32_t abase[4], bbase[2];
#pragma unroll
        for (int mf = 0; mf < 4; mf++) abase[mf] = sbase + aoff + rA[mf] * 128;
#pragma unroll
        for (int nh = 0; nh < 2; nh++) bbase[nh] = sbase + boff + rB[nh] * 128;

        int kend = (kt == 4) ? 32 : 64;
#pragma unroll
        for (int ks = 0; ks < 64; ks += 16) {
            if (ks >= kend) break;
            uint32_t cofs = ((uint32_t)(ks * 2) + kadd) ^ xorv;
            unsigned a[4][4];
#pragma unroll
            for (int mf = 0; mf < 4; mf++)
                ldsm_x4(a[mf][0], a[mf][1], a[mf][2], a[mf][3], abase[mf] + cofs);
            unsigned b[4][2];
#pragma unroll
            for (int nh = 0; nh < 2; nh++) {
                unsigned r0, r1, r2, r3;
                ldsm_x4(r0, r1, r2, r3, bbase[nh] + cofs);
                b[nh * 2][0] = r0; b[nh * 2 + 1][0] = r1;
                b[nh * 2][1] = r2; b[nh * 2 + 1][1] = r3;
            }
#pragma unroll
            for (int mf = 0; mf < 4; mf++)
#pragma unroll
                for (int nf = 0; nf < 4; nf++)
                    mma16816(acc[mf][nf], a[mf], b[nf]);
        }
        __syncthreads();   // protect buffer before next prefetch overwrites
    }

    // epilogue -> bf16
#pragma unroll
    for (int mf = 0; mf < 4; mf++) {
#pragma unroll
        for (int nf = 0; nf < 4; nf++) {
            int row = m0 + wm * 64 + mf * 16 + gr;
            int col = n0 + wn * 32 + nf * 8 + tg * 2;
            float* c = acc[mf][nf];
            *reinterpret_cast<__nv_bfloat162*>(&g_QK[(size_t)row * QKROWS + col]) =
                __floats2bfloat162_rn(c[0], c[1]);
            *reinterpret_cast<__nv_bfloat162*>(&g_QK[(size_t)(row + 8) * QKROWS + col]) =
                __floats2bfloat162_rn(c[2], c[3]);
        }
    }
}

// ---------------- attention: normalize groups, mean over slots, attn ----------------
// warp per position; lane handles memory slots m = lane and lane+32
__global__ __launch_bounds__(256) void attn_kernel(const float* __restrict__ bq,
                                                   const float* __restrict__ bk) {
    int warp = threadIdx.x >> 5, lane = threadIdx.x & 31;
    int p = blockIdx.x * 8 + warp;
    const __nv_bfloat16* qk = g_QK + (size_t)p * QKROWS;

    float qs[SQG];
#pragma unroll
    for (int jj = 0; jj < SQG; jj++) qs[jj] = 0.f;

#pragma unroll
    for (int mi = 0; mi < 2; mi++) {
        int m = lane + mi * 32;
        uint4 u0 = *reinterpret_cast<const uint4*>(qk + m * SQG);
        uint4 u1 = *reinterpret_cast<const uint4*>(qk + m * SQG + 8);
        const float4* bqv = reinterpret_cast<const float4*>(bq + m * SQG);
        float4 b0 = bqv[0], b1 = bqv[1], b2 = bqv[2], b3 = bqv[3];
        unsigned uu[8] = {u0.x, u0.y, u0.z, u0.w, u1.x, u1.y, u1.z, u1.w};
        float bb[16] = {b0.x, b0.y, b0.z, b0.w, b1.x, b1.y, b1.z, b1.w,
                        b2.x, b2.y, b2.z, b2.w, b3.x, b3.y, b3.z, b3.w};
        float qv[SQG], ss = 0.f;
#pragma unroll
        for (int h = 0; h < 8; h++) {
            __nv_bfloat162 hv = *reinterpret_cast<__nv_bfloat162*>(&uu[h]);
            float lo = __low2float(hv) + bb[2 * h];
            float hi = __high2float(hv) + bb[2 * h + 1];
            qv[2 * h] = lo; qv[2 * h + 1] = hi;
            ss += lo * lo + hi * hi;
        }
        float inv = 1.f / fmaxf(sqrtf(ss), 1e-12f);
#pragma unroll
        for (int jj = 0; jj < SQG; jj++) qs[jj] += qv[jj] * inv;
    }
#pragma unroll
    for (int off = 16; off > 0; off >>= 1)
#pragma unroll
        for (int jj = 0; jj < SQG; jj++)
            qs[jj] += __shfl_xor_sync(0xffffffffu, qs[jj], off);

#pragma unroll
    for (int mi = 0; mi < 2; mi++) {
        int m = lane + mi * 32;
        uint4 u0 = *reinterpret_cast<const uint4*>(qk + 1024 + m * SQG);
        uint4 u1 = *reinterpret_cast<const uint4*>(qk + 1024 + m * SQG + 8);
        const float4* bkv = reinterpret_cast<const float4*>(bk + m * SQG);
        float4 b0 = bkv[0], b1 = bkv[1], b2 = bkv[2], b3 = bkv[3];
        unsigned uu[8] = {u0.x, u0.y, u0.z, u0.w, u1.x, u1.y, u1.z, u1.w};
        float bb[16] = {b0.x, b0.y, b0.z, b0.w, b1.x, b1.y, b1.z, b1.w,
                        b2.x, b2.y, b2.z, b2.w, b3.x, b3.y, b3.z, b3.w};
        float ss = 0.f, dot = 0.f;
#pragma unroll
        for (int h = 0; h < 8; h++) {
            __nv_bfloat162 hv = *reinterpret_cast<__nv_bfloat162*>(&uu[h]);
            float lo = __low2float(hv) + bb[2 * h];
            float hi = __high2float(hv) + bb[2 * h + 1];
            ss += lo * lo + hi * hi;
            dot += qs[2 * h] * lo + qs[2 * h + 1] * hi;
        }
        float inv = 1.f / fmaxf(sqrtf(ss), 1e-12f);
        g_attn[(size_t)p * NMEM + m] = dot * inv * (1.f / 64.f);
    }
}

// ---------------- output: out = x + attn @ Wv + bout, written [B,256,H,W] ----------------
__global__ __launch_bounds__(256) void out_kernel(const float* __restrict__ x,
                                                  const float* __restrict__ bout,
                                                  float* __restrict__ out) {
    __shared__ float attn_s[64][65];
    __shared__ __align__(16) float wv_s[64][32];
    int p0 = blockIdx.x * 64;
    int o0 = blockIdx.y * 32;
    int tid = threadIdx.x;
    int px = tid & 63, oq = tid >> 6;

#pragma unroll
    for (int i = 0; i < 16; i++) {
        int idx = tid + i * 256;
        int pr = idx >> 6, mm = idx & 63;
        attn_s[pr][mm] = g_attn[(size_t)(p0 + pr) * NMEM + mm];
    }
#pragma unroll
    for (int i = 0; i < 8; i++) {
        int idx = tid + i * 256;
        int mm = idx >> 5, oo = idx & 31;
        wv_s[mm][oo] = g_Wv[mm * CCH + o0 + oo];
    }
    __syncthreads();

    float acc[8];
#pragma unroll
    for (int i = 0; i < 8; i++) acc[i] = 0.f;

#pragma unroll 4
    for (int m = 0; m < 64; m++) {
        float a = attn_s[px][m];
        float4 w0 = *reinterpret_cast<const float4*>(&wv_s[m][oq * 8]);
        float4 w1 = *reinterpret_cast<const float4*>(&wv_s[m][oq * 8 + 4]);
        acc[0] += a * w0.x; acc[1] += a * w0.y; acc[2] += a * w0.z; acc[3] += a * w0.w;
        acc[4] += a * w1.x; acc[5] += a * w1.y; acc[6] += a * w1.z; acc[7] += a * w1.w;
    }

    int p = p0 + px;
    int b = p >> 12, s = p & (SS - 1);
#pragma unroll
    for (int i = 0; i < 8; i++) {
        int o = o0 + oq * 8 + i;
        size_t gi = ((size_t)b * CCH + o) * SS + s;
        out[gi] = x[gi] + acc[i] + bout[o];
    }
}

// ---------------- launch ----------------
extern "C" void kernel_launch(void* const* d_in, const int* in_sizes, int n_in,
                              void* d_out, int out_size) {
    const float* x    = (const float*)d_in[0];
    const float* pos  = (const float*)d_in[1];
    const float* wq   = (const float*)d_in[2];
    const float* bq   = (const float*)d_in[3];
    const float* wk   = (const float*)d_in[4];
    const float* bk   = (const float*)d_in[5];
    const float* v    = (const float*)d_in[6];
    const float* wout = (const float*)d_in[7];
    const float* bout = (const float*)d_in[8];
    float* out = (float*)d_out;

    cudaFuncSetAttribute(gemm_qk_kernel,
                         cudaFuncAttributeMaxDynamicSharedMemorySize, SM_TOTAL);

    prep_x_kernel<<<dim3(CCH / 32, SS / 32, BB), dim3(32, 8)>>>(x);
    prep_pos_kernel<<<(MP * 32) / 256, 256>>>(pos);
    prep_w_kernel<<<(QKROWS * KPAD) / 256, 256>>>(wq, wk);
    prep_wv_kernel<<<dim3(NMEM, 4), 256>>>(v, wout);
    gemm_qk_kernel<<<dim3(MP / GBM, QKROWS / GBN), 256, SM_TOTAL>>>();
    attn_kernel<<<MP / 8, 256>>>(bq, bk);
    out_kernel<<<dim3(MP / 64, CCH / 32), 256>>>(x, bout, out);
}

// round 14
// speedup vs baseline: 1.1352x; 1.0032x over previous
#include <cuda_runtime.h>
#include <cuda_bf16.h>
#include <stdint.h>

// ---------------- problem constants ----------------
#define BB     4
#define CCH    256          // FIN
#define SS     4096         // H*W
#define MP     (BB*SS)      // 16384 positions
#define NMEM   64
#define SQG    16
#define QKROWS 2048         // 1024 q rows + 1024 k rows
#define CINR   258          // FIN + 2 pos channels
#define KPAD   288          // CINR padded: 4x64 + 1x32 k-tiles
#define NKT    5

// ---------------- scratch (device globals; no allocation) ----------------
__device__ __nv_bfloat16 g_A[(size_t)MP * KPAD];          // xp^T bf16, K padded
__device__ __nv_bfloat16 g_W[(size_t)QKROWS * KPAD];      // [wq; wk] bf16, K padded
__device__ float         g_qsum[(size_t)MP * SQG];        // sum over slots of normalized q
__device__ float         g_attn[(size_t)MP * NMEM];       // attn_mean per position
__device__ float         g_Wv[NMEM * CCH];                // v @ wout^T (fused tail)

// ---------------- PTX helpers (base sm_103 only) ----------------
__device__ __forceinline__ uint32_t smem_u32(const void* p) {
    uint32_t a;
    asm("{ .reg .u64 t; cvta.to.shared.u64 t, %1; cvt.u32.u64 %0, t; }" : "=r"(a) : "l"(p));
    return a;
}
__device__ __forceinline__ void cp16(uint32_t saddr, const void* g) {
    asm volatile("cp.async.cg.shared.global [%0], [%1], 16;\n" :: "r"(saddr), "l"(g));
}
__device__ __forceinline__ void cp_commit() {
    asm volatile("cp.async.commit_group;\n" ::: "memory");
}
template <int N> __device__ __forceinline__ void cp_wait() {
    asm volatile("cp.async.wait_group %0;\n" :: "n"(N) : "memory");
}
__device__ __forceinline__ void mma16816(float* c, const unsigned* a, const unsigned* b) {
    asm volatile(
        "mma.sync.aligned.m16n8k16.row.col.f32.bf16.bf16.f32 "
        "{%0,%1,%2,%3}, {%4,%5,%6,%7}, {%8,%9}, {%0,%1,%2,%3};\n"
        : "+f"(c[0]), "+f"(c[1]), "+f"(c[2]), "+f"(c[3])
        : "r"(a[0]), "r"(a[1]), "r"(a[2]), "r"(a[3]), "r"(b[0]), "r"(b[1]));
}
__device__ __forceinline__ void ldsm_x4(unsigned& r0, unsigned& r1, unsigned& r2,
                                        unsigned& r3, uint32_t a) {
    asm volatile("ldmatrix.sync.aligned.m8n8.x4.shared.b16 {%0,%1,%2,%3}, [%4];"
                 : "=r"(r0), "=r"(r1), "=r"(r2), "=r"(r3) : "r"(a));
}
// SW128 swizzle for 128-byte rows
__device__ __forceinline__ uint32_t swz(uint32_t off) { return off ^ ((off >> 3) & 0x70); }

// ---------------- prep: transpose x into g_A (cols 0..255) ----------------
__global__ void prep_x_kernel(const float* __restrict__ x) {
    __shared__ float tile[32][33];
    int b  = blockIdx.z;
    int c0 = blockIdx.x * 32;
    int s0 = blockIdx.y * 32;
    int tx = threadIdx.x, ty = threadIdx.y;  // 32 x 8
    const float* xb = x + (size_t)b * CCH * SS;
#pragma unroll
    for (int i = 0; i < 4; i++) {
        int c = c0 + ty + i * 8;
        tile[ty + i * 8][tx] = xb[(size_t)c * SS + s0 + tx];
    }
    __syncthreads();
#pragma unroll
    for (int i = 0; i < 4; i++) {
        int s = s0 + ty + i * 8;
        int p = b * SS + s;
        g_A[(size_t)p * KPAD + c0 + tx] = __float2bfloat16(tile[tx][ty + i * 8]);
    }
}

// ---------------- prep: pos channels + zero pad (cols 256..287) ----------------
__global__ void prep_pos_kernel(const float* __restrict__ pos) {
    int g = blockIdx.x * blockDim.x + threadIdx.x;   // MP*32 threads
    int p = g >> 5, cc = g & 31;
    int s = p & (SS - 1);
    float v = 0.f;
    if (cc == 0)      v = pos[s];
    else if (cc == 1) v = pos[SS + s];
    g_A[(size_t)p * KPAD + 256 + cc] = __float2bfloat16(v);
}

// ---------------- prep: weights [wq; wk] -> bf16 padded ----------------
__global__ void prep_w_kernel(const float* __restrict__ wq, const float* __restrict__ wk) {
    int g = blockIdx.x * blockDim.x + threadIdx.x;   // QKROWS*KPAD threads
    int r = g / KPAD, c = g % KPAD;
    float v = 0.f;
    if (c < CINR) v = (r < 1024) ? wq[r * CINR + c] : wk[(r - 1024) * CINR + c];
    g_W[g] = __float2bfloat16(v);
}

// ---------------- prep: Wv[m][o] = sum_f v[m][f] * wout[o][f] ----------------
__global__ __launch_bounds__(256) void prep_wv_kernel(const float* __restrict__ v,
                                                      const float* __restrict__ wout) {
    __shared__ float vs[CCH];
    __shared__ float part[256];
    int m  = blockIdx.x;
    int oc = blockIdx.y;          // chunk of 64 outputs
    int tid = threadIdx.x;
    int ol = tid & 63, fq = tid >> 6;
    vs[tid] = v[m * CCH + tid];
    __syncthreads();
    int o = oc * 64 + ol;
    const float4* wr = reinterpret_cast<const float4*>(wout + (size_t)o * CCH + fq * 64);
    float acc = 0.f;
#pragma unroll
    for (int i = 0; i < 16; i++) {
        float4 w = wr[i];
        int f = fq * 64 + i * 4;
        acc += vs[f] * w.x + vs[f + 1] * w.y + vs[f + 2] * w.z + vs[f + 3] * w.w;
    }
    part[tid] = acc;
    __syncthreads();
    if (fq == 0)
        g_Wv[m * CCH + o] = part[ol] + part[ol + 64] + part[ol + 128] + part[ol + 192];
}

// ---------------- fused GEMM + normalization epilogues ----------------
// Same 128x128 tiling as the 141.8us champion. Two launches:
//   mode 0 (q): n rows [0,1024).  Epilogue: per-slot normalize (quad shuffle),
//               accumulate sum of normalized q into smem, atomic-flush to g_qsum.
//   mode 1 (k): n rows [1024,2048). Epilogue: normalize k, dot with g_qsum,
//               write g_attn directly. No QK tensor anywhere.
#define GBM 128
#define GBN 128
#define STAGE_A   16384
#define SM_AOFF(s) ((s) * STAGE_A)
#define SM_BOFF(s) (32768 + (s) * STAGE_A)
#define QS_OFF    65536                 // 128 x 17 x 4 = 8704
#define BIAS_OFF  74240                 // 1024 x 4
#define SM_TOTAL  78336
#define QSP       17

__device__ __forceinline__ void stage_tile(uint32_t sbase, uint32_t aoff, uint32_t boff,
                                           int m0, int n0, int kt, int tid) {
    int kk = kt * 64;
    if (kt < 4) {
#pragma unroll
        for (int i = 0; i < 4; i++) {
            int idx = tid + i * 256;
            int row = idx >> 3, ch = idx & 7;
            uint32_t so = swz(row * 128 + ch * 16);
            cp16(sbase + aoff + so, &g_A[(size_t)(m0 + row) * KPAD + kk + ch * 8]);
            cp16(sbase + boff + so, &g_W[(size_t)(n0 + row) * KPAD + kk + ch * 8]);
        }
    } else {
#pragma unroll
        for (int i = 0; i < 2; i++) {
            int idx = tid + i * 256;
            int row = idx >> 2, ch = idx & 3;
            uint32_t so = swz(row * 128 + ch * 16);
            cp16(sbase + aoff + so, &g_A[(size_t)(m0 + row) * KPAD + kk + ch * 8]);
            cp16(sbase + boff + so, &g_W[(size_t)(n0 + row) * KPAD + kk + ch * 8]);
        }
    }
    cp_commit();
}

__global__ __launch_bounds__(256, 2) void gemm_qk_kernel(int nbase, int isK,
                                                         const float* __restrict__ bias) {
    extern __shared__ __align__(1024) char smem[];
    uint32_t sbase = smem_u32(smem);
    float* qs_s   = reinterpret_cast<float*>(smem + QS_OFF);
    float* bias_s = reinterpret_cast<float*>(smem + BIAS_OFF);
    int tid  = threadIdx.x;
    int warp = tid >> 5, lane = tid & 31;
    int wm = warp & 1, wn = warp >> 1;      // warp grid 2(m) x 4(n)
    int gr = lane >> 2, tg = lane & 3;
    int m0 = blockIdx.x * GBM;
    int n0 = nbase + blockIdx.y * GBN;

    // ldmatrix lane geometry
    int j  = lane >> 3;
    int jm = j & 1;
    uint32_t kadd = (uint32_t)(j >> 1) * 16;
    uint32_t xorv = (uint32_t)(lane & 7) << 4;
    int rA[4], rB[2];
#pragma unroll
    for (int mf = 0; mf < 4; mf++) rA[mf] = wm * 64 + mf * 16 + jm * 8 + (lane & 7);
#pragma unroll
    for (int nh = 0; nh < 2; nh++) rB[nh] = wn * 32 + nh * 16 + jm * 8 + (lane & 7);

    float acc[4][4][4];
#pragma unroll
    for (int i = 0; i < 4; i++)
#pragma unroll
        for (int jj = 0; jj < 4; jj++)
#pragma unroll
            for (int q = 0; q < 4; q++) acc[i][jj][q] = 0.f;

    // prologue: stage tile 0; zero qs smem; load bias
    stage_tile(sbase, SM_AOFF(0), SM_BOFF(0), m0, n0, 0, tid);
    for (int i = tid; i < GBM * QSP; i += 256) qs_s[i] = 0.f;
    for (int i = tid; i < 1024; i += 256) bias_s[i] = bias[i];

    for (int kt = 0; kt < NKT; kt++) {
        uint32_t aoff = SM_AOFF(kt & 1);
        uint32_t boff = SM_BOFF(kt & 1);
        if (kt + 1 < NKT) {
            stage_tile(sbase, SM_AOFF((kt + 1) & 1), SM_BOFF((kt + 1) & 1),
                       m0, n0, kt + 1, tid);
            cp_wait<1>();
        } else {
            cp_wait<0>();
        }
        __syncthreads();

        uint32_t abase[4], bbase[2];
#pragma unroll
        for (int mf = 0; mf < 4; mf++) abase[mf] = sbase + aoff + rA[mf] * 128;
#pragma unroll
        for (int nh = 0; nh < 2; nh++) bbase[nh] = sbase + boff + rB[nh] * 128;

        int kend = (kt == 4) ? 32 : 64;
#pragma unroll
        for (int ks = 0; ks < 64; ks += 16) {
            if (ks >= kend) break;
            uint32_t cofs = ((uint32_t)(ks * 2) + kadd) ^ xorv;
            unsigned a[4][4];
#pragma unroll
            for (int mf = 0; mf < 4; mf++)
                ldsm_x4(a[mf][0], a[mf][1], a[mf][2], a[mf][3], abase[mf] + cofs);
            unsigned b[4][2];
#pragma unroll
            for (int nh = 0; nh < 2; nh++) {
                unsigned r0, r1, r2, r3;
                ldsm_x4(r0, r1, r2, r3, bbase[nh] + cofs);
                b[nh * 2][0] = r0; b[nh * 2 + 1][0] = r1;
                b[nh * 2][1] = r2; b[nh * 2 + 1][1] = r3;
            }
#pragma unroll
            for (int mf = 0; mf < 4; mf++)
#pragma unroll
                for (int nf = 0; nf < 4; nf++)
                    mma16816(acc[mf][nf], a[mf], b[nf]);
        }
        __syncthreads();
    }

    // ---- fused epilogue (math identical to the R12-verified version) ----
    int j0 = tg * 2;
    if (!isK) {
        float qp[8][4];
#pragma unroll
        for (int a1 = 0; a1 < 8; a1++)
#pragma unroll
            for (int a2 = 0; a2 < 4; a2++) qp[a1][a2] = 0.f;
#pragma unroll
        for (int p = 0; p < 2; p++) {
            int sl16 = (wn * 2 + p) * 16;
            float b0 = bias_s[sl16 + j0];
            float b1 = bias_s[sl16 + j0 + 1];
            float b2 = bias_s[sl16 + j0 + 8];
            float b3 = bias_s[sl16 + j0 + 9];
#pragma unroll
            for (int mf = 0; mf < 4; mf++) {
#pragma unroll
                for (int h = 0; h < 2; h++) {
                    float v0 = acc[mf][2 * p][2 * h] + b0;
                    float v1 = acc[mf][2 * p][2 * h + 1] + b1;
                    float v2 = acc[mf][2 * p + 1][2 * h] + b2;
                    float v3 = acc[mf][2 * p + 1][2 * h + 1] + b3;
                    float ssq = v0 * v0 + v1 * v1 + v2 * v2 + v3 * v3;
                    ssq += __shfl_xor_sync(0xffffffffu, ssq, 1);
                    ssq += __shfl_xor_sync(0xffffffffu, ssq, 2);
                    float inv = 1.f / fmaxf(sqrtf(ssq), 1e-12f);
                    qp[mf * 2 + h][0] += v0 * inv;
                    qp[mf * 2 + h][1] += v1 * inv;
                    qp[mf * 2 + h][2] += v2 * inv;
                    qp[mf * 2 + h][3] += v3 * inv;
                }
            }
        }
#pragma unroll
        for (int mf = 0; mf < 4; mf++) {
#pragma unroll
            for (int h = 0; h < 2; h++) {
                int row = wm * 64 + mf * 16 + gr + h * 8;
                atomicAdd(&qs_s[row * QSP + j0],     qp[mf * 2 + h][0]);
                atomicAdd(&qs_s[row * QSP + j0 + 1], qp[mf * 2 + h][1]);
                atomicAdd(&qs_s[row * QSP + j0 + 8], qp[mf * 2 + h][2]);
                atomicAdd(&qs_s[row * QSP + j0 + 9], qp[mf * 2 + h][3]);
            }
        }
        __syncthreads();
        for (int idx = tid; idx < GBM * SQG; idx += 256) {
            int row = idx >> 4, col = idx & 15;
            atomicAdd(&g_qsum[(size_t)(m0 + row) * SQG + col], qs_s[row * QSP + col]);
        }
    } else {
        int slotbase = blockIdx.y * 8;
#pragma unroll
        for (int mf = 0; mf < 4; mf++) {
#pragma unroll
            for (int h = 0; h < 2; h++) {
                int row = wm * 64 + mf * 16 + gr + h * 8;
                const float* qsr = &g_qsum[(size_t)(m0 + row) * SQG];
                float q0 = qsr[j0], q1 = qsr[j0 + 1], q2 = qsr[j0 + 8], q3 = qsr[j0 + 9];
#pragma unroll
                for (int p = 0; p < 2; p++) {
                    int sl16 = (wn * 2 + p) * 16;
                    float v0 = acc[mf][2 * p][2 * h] + bias_s[sl16 + j0];
                    float v1 = acc[mf][2 * p][2 * h + 1] + bias_s[sl16 + j0 + 1];
                    float v2 = acc[mf][2 * p + 1][2 * h] + bias_s[sl16 + j0 + 8];
                    float v3 = acc[mf][2 * p + 1][2 * h + 1] + bias_s[sl16 + j0 + 9];
                    float ssq = v0 * v0 + v1 * v1 + v2 * v2 + v3 * v3;
                    float dl  = v0 * q0 + v1 * q1 + v2 * q2 + v3 * q3;
                    ssq += __shfl_xor_sync(0xffffffffu, ssq, 1);
                    ssq += __shfl_xor_sync(0xffffffffu, ssq, 2);
                    dl  += __shfl_xor_sync(0xffffffffu, dl, 1);
                    dl  += __shfl_xor_sync(0xffffffffu, dl, 2);
                    float inv = 1.f / fmaxf(sqrtf(ssq), 1e-12f);
                    if (tg == 0)
                        g_attn[(size_t)(m0 + row) * NMEM + slotbase + wn * 2 + p] =
                            dl * inv * (1.f / 64.f);
                }
            }
        }
    }
}

// ---------------- output: out = x + attn @ Wv + bout, written [B,256,H,W] ----------------
__global__ __launch_bounds__(256) void out_kernel(const float* __restrict__ x,
                                                  const float* __restrict__ bout,
                                                  float* __restrict__ out) {
    __shared__ float attn_s[64][65];
    __shared__ __align__(16) float wv_s[64][32];
    int p0 = blockIdx.x * 64;
    int o0 = blockIdx.y * 32;
    int tid = threadIdx.x;
    int px = tid & 63, oq = tid >> 6;

#pragma unroll
    for (int i = 0; i < 16; i++) {
        int idx = tid + i * 256;
        int pr = idx >> 6, mm = idx & 63;
        attn_s[pr][mm] = g_attn[(size_t)(p0 + pr) * NMEM + mm];
    }
#pragma unroll
    for (int i = 0; i < 8; i++) {
        int idx = tid + i * 256;
        int mm = idx >> 5, oo = idx & 31;
        wv_s[mm][oo] = g_Wv[mm * CCH + o0 + oo];
    }
    __syncthreads();

    float acc[8];
#pragma unroll
    for (int i = 0; i < 8; i++) acc[i] = 0.f;

#pragma unroll 4
    for (int m = 0; m < 64; m++) {
        float a = attn_s[px][m];
        float4 w0 = *reinterpret_cast<const float4*>(&wv_s[m][oq * 8]);
        float4 w1 = *reinterpret_cast<const float4*>(&wv_s[m][oq * 8 + 4]);
        acc[0] += a * w0.x; acc[1] += a * w0.y; acc[2] += a * w0.z; acc[3] += a * w0.w;
        acc[4] += a * w1.x; acc[5] += a * w1.y; acc[6] += a * w1.z; acc[7] += a * w1.w;
    }

    int p = p0 + px;
    int b = p >> 12, s = p & (SS - 1);
#pragma unroll
    for (int i = 0; i < 8; i++) {
        int o = o0 + oq * 8 + i;
        size_t gi = ((size_t)b * CCH + o) * SS + s;
        out[gi] = x[gi] + acc[i] + bout[o];
    }
}

// ---------------- launch ----------------
extern "C" void kernel_launch(void* const* d_in, const int* in_sizes, int n_in,
                              void* d_out, int out_size) {
    const float* x    = (const float*)d_in[0];
    const float* pos  = (const float*)d_in[1];
    const float* wq   = (const float*)d_in[2];
    const float* bq   = (const float*)d_in[3];
    const float* wk   = (const float*)d_in[4];
    const float* bk   = (const float*)d_in[5];
    const float* v    = (const float*)d_in[6];
    const float* wout = (const float*)d_in[7];
    const float* bout = (const float*)d_in[8];
    float* out = (float*)d_out;

    cudaFuncSetAttribute(gemm_qk_kernel,
                         cudaFuncAttributeMaxDynamicSharedMemorySize, SM_TOTAL);
    void* qsum_ptr = nullptr;
    cudaGetSymbolAddress(&qsum_ptr, g_qsum);

    prep_x_kernel<<<dim3(CCH / 32, SS / 32, BB), dim3(32, 8)>>>(x);
    prep_pos_kernel<<<(MP * 32) / 256, 256>>>(pos);
    prep_w_kernel<<<(QKROWS * KPAD) / 256, 256>>>(wq, wk);
    prep_wv_kernel<<<dim3(NMEM, 4), 256>>>(v, wout);
    cudaMemsetAsync(qsum_ptr, 0, (size_t)MP * SQG * sizeof(float), 0);
    gemm_qk_kernel<<<dim3(MP / GBM, 1024 / GBN), 256, SM_TOTAL>>>(0, 0, bq);
    gemm_qk_kernel<<<dim3(MP / GBM, 1024 / GBN), 256, SM_TOTAL>>>(1024, 1, bk);
    out_kernel<<<dim3(MP / 64, CCH / 32), 256>>>(x, bout, out);
}